// round 12
// baseline (speedup 1.0000x reference)
#include <cuda_runtime.h>
#include <cuda_fp16.h>
#include <math.h>

// Problem constants
#define NN_ 50000
#define EE_ 600000
#define HH_ 128
#define FF_ 256
#define QQ_ 64
#define NH_ (NN_ * HH_)
#define TP 136   // K=128 tile row pad: 272 B stride -> ldmatrix conflict-free

// ---------------- scratch (device globals; no dynamic allocation) ----------
__device__ __half g_h0 [4 * NH_];
__device__ __half g_h1 [4 * NH_];
__device__ __half g_hA [4 * NH_];
__device__ __half g_h2 [4 * NH_];
__device__ __half g_agg[8 * NH_];
__device__ __half g_hs [16 * NH_];
__device__ float  g_s  [16 * NN_];
__device__ __half g_x16[2 * NN_ * FF_];

__device__ __half g_wf16 [2 * HH_ * FF_];        // [s][n=128][k=256]
__device__ __half g_cw16 [8 * HH_ * HH_];        // [m][n=128][k=128]
__device__ __half g_w116 [4 * QQ_ * HH_];        // [m][n=64][k=128]
__device__ __half g_wc16 [2 * HH_ * 3 * HH_];    // [s][n=128][k=384]

__device__ int   g_cnt_in [8 * NN_];
__device__ int   g_cnt_out[8 * NN_];
__device__ int   g_cursor [8 * NN_];
__device__ int   g_off    [8 * (NN_ + 1)];
__device__ int   g_csr    [8 * EE_];
__device__ float g_din    [8 * NN_];
__device__ float g_dout   [8 * NN_];

// ---------------- helpers ---------------------------------------------------
__device__ __forceinline__ const int* edge_ptr_dev(const int* e_attr, const int* e_stru,
                                                   int p, int which) {
    int c = p >> 1, r = p & 1;
    int sign = c >> 1;
    const int* E = (c & 1) ? e_stru : e_attr;
    return E + ((size_t)((sign * 2 + r) * 2 + which)) * EE_;
}

// ---------------- prep kernels ----------------------------------------------
__global__ void prep_weights_kernel(const float* __restrict__ Wf, const float* __restrict__ convW,
                                    const float* __restrict__ attnW1, const float* __restrict__ Wc,
                                    __half* __restrict__ wf16, __half* __restrict__ cw16,
                                    __half* __restrict__ w116, __half* __restrict__ wc16) {
    const int NWF = 2 * HH_ * FF_;
    const int NCW = 8 * HH_ * HH_;
    const int NW1 = 4 * QQ_ * HH_;
    const int NWC = 2 * HH_ * 3 * HH_;
    for (int i = blockIdx.x * blockDim.x + threadIdx.x;
         i < NWF + NCW + NW1 + NWC; i += gridDim.x * blockDim.x) {
        if (i < NWF) {
            wf16[i] = __float2half_rn(Wf[i]);
        } else if (i < NWF + NCW) {
            int j = i - NWF;
            int m = j / (HH_ * HH_), t = j % (HH_ * HH_);
            int n = t / HH_, k = t % HH_;
            cw16[j] = __float2half_rn(convW[m * HH_ * HH_ + k * HH_ + n]);
        } else if (i < NWF + NCW + NW1) {
            int j = i - NWF - NCW;
            int m = j / (QQ_ * HH_), t = j % (QQ_ * HH_);
            int n = t / HH_, k = t % HH_;
            w116[j] = __float2half_rn(attnW1[m * HH_ * QQ_ + k * QQ_ + n]);
        } else {
            int j = i - NWF - NCW - NW1;
            wc16[j] = __float2half_rn(Wc[j]);
        }
    }
}

__global__ void convert_x_kernel(const float* __restrict__ xa, const float* __restrict__ xs,
                                 __half* __restrict__ x16) {
    const int Q4 = NN_ * FF_ / 4;
    for (int i = blockIdx.x * blockDim.x + threadIdx.x; i < Q4; i += gridDim.x * blockDim.x) {
        float4 va = ((const float4*)xa)[i];
        float4 vs = ((const float4*)xs)[i];
        __half2 ha0 = __floats2half2_rn(va.x, va.y), ha1 = __floats2half2_rn(va.z, va.w);
        __half2 hs0 = __floats2half2_rn(vs.x, vs.y), hs1 = __floats2half2_rn(vs.z, vs.w);
        ((uint2*)x16)[i] = make_uint2(*(unsigned*)&ha0, *(unsigned*)&ha1);
        ((uint2*)(x16 + (size_t)NN_ * FF_))[i] = make_uint2(*(unsigned*)&hs0, *(unsigned*)&hs1);
    }
}

// ---------------- CSR-build kernels (batched over 8 pairs) ------------------
__global__ void zero2_kernel(int* a, int* b, int n) {
    for (int i = blockIdx.x * blockDim.x + threadIdx.x; i < n; i += gridDim.x * blockDim.x) {
        a[i] = 0;
        b[i] = 0;
    }
}

__global__ void hist_all_kernel(const int* __restrict__ e_attr, const int* __restrict__ e_stru,
                                int* __restrict__ cnt_out, int* __restrict__ cnt_in) {
    int p = blockIdx.y;
    const int* src = edge_ptr_dev(e_attr, e_stru, p, 0);
    const int* dst = edge_ptr_dev(e_attr, e_stru, p, 1);
    int* co = cnt_out + p * NN_;
    int* ci = cnt_in  + p * NN_;
    for (int i = blockIdx.x * blockDim.x + threadIdx.x; i < EE_; i += gridDim.x * blockDim.x) {
        atomicAdd(&co[src[i]], 1);
        atomicAdd(&ci[dst[i]], 1);
    }
}

// scan + degree normalization in one kernel (8 blocks, one per pair)
__global__ void scan_deg_kernel(const int* __restrict__ cnt_all, const int* __restrict__ cout_all,
                                int* __restrict__ off_all, int* __restrict__ cur_all,
                                float* __restrict__ din_all, float* __restrict__ dout_all) {
    __shared__ int sh[1024];
    const int p = blockIdx.x;
    const int* cnt  = cnt_all + p * NN_;
    const int* cout = cout_all + p * NN_;
    int* off = off_all + p * (NN_ + 1);
    int* cur = cur_all + p * NN_;
    float* din  = din_all + p * NN_;
    float* dout = dout_all + p * NN_;
    const int t  = threadIdx.x;
    const int CH = (NN_ + 1023) / 1024;
    const int base = t * CH;
    int s = 0;
    for (int i = 0; i < CH; i++) {
        int idx = base + i;
        if (idx < NN_) {
            int a = cnt[idx];
            int b = cout[idx];
            din [idx] = rsqrtf((float)(a < 1 ? 1 : a));
            dout[idx] = rsqrtf((float)(b < 1 ? 1 : b));
            s += a;
        }
    }
    sh[t] = s;
    __syncthreads();
    for (int d = 1; d < 1024; d <<= 1) {
        int v = (t >= d) ? sh[t - d] : 0;
        __syncthreads();
        sh[t] += v;
        __syncthreads();
    }
    int run = (t == 0) ? 0 : sh[t - 1];
    for (int i = 0; i < CH; i++) {
        int idx = base + i;
        if (idx < NN_) { off[idx] = run; cur[idx] = run; run += cnt[idx]; }
    }
    if (t == 0) off[NN_] = sh[1023];
}

__global__ void scatter_all_kernel(const int* __restrict__ e_attr, const int* __restrict__ e_stru,
                                   int* __restrict__ cursor, int* __restrict__ csr) {
    int p = blockIdx.y;
    const int* src = edge_ptr_dev(e_attr, e_stru, p, 0);
    const int* dst = edge_ptr_dev(e_attr, e_stru, p, 1);
    int* cu = cursor + p * NN_;
    int* cs = csr + (size_t)p * EE_;
    for (int i = blockIdx.x * blockDim.x + threadIdx.x; i < EE_; i += gridDim.x * blockDim.x) {
        int pos = atomicAdd(&cu[dst[i]], 1);
        cs[pos] = src[i];
    }
}

// ---------------- batched CSR gather: half-warp per edge, LDG.128 -----------
__global__ void gather_all_kernel(const __half* __restrict__ hin_base,
                                  const int* __restrict__ off_all,
                                  const int* __restrict__ csr_all,
                                  const float* __restrict__ dout_all,
                                  __half* __restrict__ agg) {
    int p = blockIdx.y;
    int c = p >> 1;
    const __half* h = hin_base + (size_t)c * NH_;
    const int* off = off_all + p * (NN_ + 1);
    const int* csr = csr_all + (size_t)p * EE_;
    const float* dout = dout_all + p * NN_;
    __half* out = agg + (size_t)p * NH_;

    int warp = (blockIdx.x * blockDim.x + threadIdx.x) >> 5;
    int lane = threadIdx.x & 31;
    if (warp >= NN_) return;
    int b = off[warp], e = off[warp + 1];
    const int hf = lane >> 4;        // half-warp id: 0 -> edge i, 1 -> edge i+1
    const int li = lane & 15;        // uint4 index within row (16 x 8 halves = 128)
    const uint4* h16 = (const uint4*)h;

    float acc[8];
#pragma unroll
    for (int j = 0; j < 8; j++) acc[j] = 0.f;

    int i = b;
    for (; i + 1 < e; i += 2) {
        int s = csr[i + hf];
        float w = dout[s];
        uint4 v = h16[(size_t)s * 16 + li];
        const __half2* hv = (const __half2*)&v;
#pragma unroll
        for (int j = 0; j < 4; j++) {
            float2 f = __half22float2(hv[j]);
            acc[2 * j]     += w * f.x;
            acc[2 * j + 1] += w * f.y;
        }
    }
    if (i < e && hf == 0) {
        int s = csr[i];
        float w = dout[s];
        uint4 v = h16[(size_t)s * 16 + li];
        const __half2* hv = (const __half2*)&v;
#pragma unroll
        for (int j = 0; j < 4; j++) {
            float2 f = __half22float2(hv[j]);
            acc[2 * j]     += w * f.x;
            acc[2 * j + 1] += w * f.y;
        }
    }
#pragma unroll
    for (int j = 0; j < 8; j++) acc[j] += __shfl_xor_sync(0xffffffffu, acc[j], 16);
    if (hf == 0) {
        uint4 st;
        __half2* sp = (__half2*)&st;
#pragma unroll
        for (int j = 0; j < 4; j++) sp[j] = __floats2half2_rn(acc[2 * j], acc[2 * j + 1]);
        ((uint4*)out)[(size_t)warp * 16 + li] = st;
    }
}

// ---------------- fp16 MMA / async-copy / ldmatrix helpers ------------------
__device__ __forceinline__ void mma16(float* c, unsigned a0, unsigned a1, unsigned a2,
                                      unsigned a3, unsigned b0, unsigned b1) {
    asm volatile(
        "mma.sync.aligned.m16n8k16.row.col.f32.f16.f16.f32 "
        "{%0,%1,%2,%3},{%4,%5,%6,%7},{%8,%9},{%0,%1,%2,%3};"
        : "+f"(c[0]), "+f"(c[1]), "+f"(c[2]), "+f"(c[3])
        : "r"(a0), "r"(a1), "r"(a2), "r"(a3), "r"(b0), "r"(b1));
}

__device__ __forceinline__ unsigned smem_u32(const void* p) {
    return (unsigned)__cvta_generic_to_shared(p);
}
__device__ __forceinline__ void cp16(unsigned s, const void* g) {
    asm volatile("cp.async.ca.shared.global [%0], [%1], 16;" :: "r"(s), "l"(g));
}
__device__ __forceinline__ void cp_commit() { asm volatile("cp.async.commit_group;"); }
template <int N>
__device__ __forceinline__ void cp_wait() { asm volatile("cp.async.wait_group %0;" :: "n"(N)); }

__device__ __forceinline__ void ldsm4(unsigned& r0, unsigned& r1, unsigned& r2, unsigned& r3,
                                      unsigned a) {
    asm volatile("ldmatrix.sync.aligned.m8n8.x4.shared.b16 {%0,%1,%2,%3}, [%4];"
                 : "=r"(r0), "=r"(r1), "=r"(r2), "=r"(r3) : "r"(a));
}

__device__ __forceinline__ unsigned frag_addr(const __half (*T)[TP], int r0, int kk, int lane) {
    int lr = lane & 7;
    int sel = lane >> 3;
    int row = r0 + ((sel & 1) << 3) + lr;
    int col = kk + ((sel & 2) << 2);
    return smem_u32(&T[row][col]);
}

// full K=128 MMA pass over resident tiles (no syncs inside)
template <int NF>
__device__ __forceinline__ void mma_k128(const __half (*Am)[TP], int mbase,
                                         const __half (*Bm)[TP], int nbase,
                                         float (&acc)[2][NF][4], int lane) {
#pragma unroll
    for (int kk = 0; kk < 128; kk += 16) {
        unsigned a[2][4];
#pragma unroll
        for (int mf = 0; mf < 2; mf++)
            ldsm4(a[mf][0], a[mf][1], a[mf][2], a[mf][3],
                  frag_addr(Am, mbase + mf * 16, kk, lane));
        unsigned b0[NF], b1[NF];
#pragma unroll
        for (int pr = 0; pr < NF / 2; pr++)
            ldsm4(b0[2 * pr], b0[2 * pr + 1], b1[2 * pr], b1[2 * pr + 1],
                  frag_addr(Bm, nbase + pr * 16, kk, lane));
#pragma unroll
        for (int nf = 0; nf < NF; nf++) {
            mma16(acc[0][nf], a[0][0], a[0][1], a[0][2], a[0][3], b0[nf], b1[nf]);
            mma16(acc[1][nf], a[1][0], a[1][1], a[1][2], a[1][3], b0[nf], b1[nf]);
        }
    }
}

// K=128 tile copies: 256 threads, each thread covers one half-row (64 halves = 8 x cp16)
__device__ __forceinline__ void copy128_A(__half (*dst)[TP], const __half* A, int ld,
                                          int block_m, int k0, int tid, int M) {
    int row = tid & 127;
    int hb = tid >> 7;
    int gm = block_m + row;
    unsigned sa = smem_u32(&dst[row][hb * 64]);
    if (gm < M) {
        const __half* gp = A + (size_t)gm * ld + k0 + hb * 64;
#pragma unroll
        for (int j = 0; j < 8; j++) cp16(sa + j * 16, gp + j * 8);
    } else {
#pragma unroll
        for (int j = 0; j < 8; j++) *(uint4*)&dst[row][hb * 64 + j * 8] = make_uint4(0, 0, 0, 0);
    }
}
__device__ __forceinline__ void copy128_B(__half (*dst)[TP], const __half* B, int ld,
                                          int k0, int tid) {
    int row = tid & 127;
    int hb = tid >> 7;
    unsigned sb = smem_u32(&dst[row][hb * 64]);
    const __half* gp = B + (size_t)row * ld + k0 + hb * 64;
#pragma unroll
    for (int j = 0; j < 8; j++) cp16(sb + j * 16, gp + j * 8);
}

// ---------------- h0 GEMM: h0 = tanh(x16 @ Wf16^T) -> fp16 ------------------
__global__ __launch_bounds__(256)
void h0_gemm_kernel(const __half* __restrict__ x16, const __half* __restrict__ wf16,
                    __half* __restrict__ h0b) {
    extern __shared__ char smraw[];
    __half (*As)[TP] = (__half(*)[TP])(smraw);
    __half (*Bs)[TP] = (__half(*)[TP])(smraw + 128 * TP * 2);

    const int c = blockIdx.y;
    const int s = c >> 1;
    const __half* A = x16 + (size_t)(c & 1) * NN_ * FF_;
    const __half* B = wf16 + (size_t)s * HH_ * FF_;
    __half* C = h0b + (size_t)c * NH_;

    const int tid  = threadIdx.x;
    const int lane = tid & 31;
    const int warp = tid >> 5;
    const int grp  = lane >> 2;
    const int tig  = lane & 3;
    const int mbase = (warp >> 1) * 32;
    const int nbase = (warp & 1) * 64;
    const int block_m = blockIdx.x * 128;

    float acc[2][8][4];
#pragma unroll
    for (int mf = 0; mf < 2; mf++)
#pragma unroll
        for (int nf = 0; nf < 8; nf++)
#pragma unroll
            for (int q = 0; q < 4; q++) acc[mf][nf][q] = 0.f;

#pragma unroll
    for (int k = 0; k < 2; k++) {
        copy128_A(As, A, FF_, block_m, k * 128, tid, NN_);
        copy128_B(Bs, B, FF_, k * 128, tid);
        cp_commit();
        cp_wait<0>();
        __syncthreads();
        mma_k128<8>(As, mbase, Bs, nbase, acc, lane);
        __syncthreads();
    }
#pragma unroll
    for (int mf = 0; mf < 2; mf++) {
        int r0 = block_m + mbase + mf * 16 + grp;
#pragma unroll
        for (int nf = 0; nf < 8; nf++) {
            int col = nbase + nf * 8 + tig * 2;
#pragma unroll
            for (int half = 0; half < 2; half++) {
                int r = r0 + half * 8;
                if (r >= NN_) continue;
                *(__half2*)(C + (size_t)r * HH_ + col) =
                    __floats2half2_rn(tanhf(acc[mf][nf][half * 2 + 0]),
                                      tanhf(acc[mf][nf][half * 2 + 1]));
            }
        }
    }
}

// ---------------- batched fused conv GEMM + attention score -----------------
// PHASE 0: blockIdx.y = q in 0..15: c=q>>2, li=(q>>1)&1 (li=0 -> l=1, li=1 -> l=0), r=q&1
// PHASE 1: blockIdx.y = q in 0..7:  c=q>>1, r=q&1, l=1
template <int PHASE>
__global__ __launch_bounds__(256)
void het_all_kernel(const __half* __restrict__ agg,
                    const __half* __restrict__ cw16, const float* __restrict__ convB,
                    const __half* __restrict__ w116, const float* __restrict__ attnB1,
                    const float* __restrict__ attnW2,
                    const float* __restrict__ din_all,
                    __half* __restrict__ hs_all, float* __restrict__ s_all) {
    extern __shared__ char smraw[];
    __half (*As)[TP]  = (__half(*)[TP])(smraw);
    __half (*Bs)[TP]  = (__half(*)[TP])(smraw + 128 * TP * 2);
    __half (*HSs)[TP] = (__half(*)[TP])(smraw + 2 * 128 * TP * 2);
    float* s_sm = (float*)(smraw + 3 * 128 * TP * 2);

    const int q = blockIdx.y;
    int c, l, r;
    if (PHASE == 0) { c = q >> 2; l = ((q >> 1) & 1) ? 0 : 1; r = q & 1; }
    else            { c = q >> 1; l = 1; r = q & 1; }
    const int s = c >> 1;
    const int p = c * 2 + r;
    const int m1 = (s * 2 + l) * 2 + r;
    const int m2 = s * 2 + l;

    const __half* A   = agg + (size_t)p * NH_;
    const __half* W   = cw16 + (size_t)m1 * HH_ * HH_;
    const float* bias = convB + (size_t)m1 * HH_;
    const __half* W1  = w116 + (size_t)m2 * QQ_ * HH_;
    const float* b1   = attnB1 + (size_t)m2 * QQ_;
    const float* w2   = attnW2 + (size_t)m2 * QQ_;
    const float* din  = din_all + p * NN_;
    __half* hs_out = hs_all + (size_t)q * NH_;
    float* s_out  = s_all + (size_t)q * NN_;

    const int tid  = threadIdx.x;
    const int lane = tid & 31;
    const int warp = tid >> 5;
    const int grp  = lane >> 2;
    const int tig  = lane & 3;
    const int wn   = warp & 1;
    const int mbase = (warp >> 1) * 32;
    const int block_m = blockIdx.x * 128;

    if (tid < 128) s_sm[tid] = 0.f;

    // ---- stage 1: conv GEMM, whole K=128 resident ----
    float acc[2][8][4];
#pragma unroll
    for (int mf = 0; mf < 2; mf++)
#pragma unroll
        for (int nf = 0; nf < 8; nf++)
#pragma unroll
            for (int qq = 0; qq < 4; qq++) acc[mf][nf][qq] = 0.f;

    copy128_A(As, A, HH_, block_m, 0, tid, NN_);
    copy128_B(Bs, W, HH_, 0, tid);
    cp_commit();
    cp_wait<0>();
    __syncthreads();
    mma_k128<8>(As, mbase, Bs, wn * 64, acc, lane);
    __syncthreads();   // all stage-1 reads of Bs done (Bs reused for W1 below)

    // stage-1 epilogue: hs = acc*din + b -> fp16 global + HSs[row][col]
#pragma unroll
    for (int mf = 0; mf < 2; mf++) {
        int rl0 = mbase + mf * 16 + grp;
#pragma unroll
        for (int nf = 0; nf < 8; nf++) {
            int col = wn * 64 + nf * 8 + tig * 2;
            float bc0 = bias[col], bc1 = bias[col + 1];
#pragma unroll
            for (int half = 0; half < 2; half++) {
                int rl = rl0 + half * 8;
                int rg = block_m + rl;
                float rs = (rg < NN_) ? din[rg] : 0.f;
                float v0 = acc[mf][nf][half * 2 + 0] * rs + bc0;
                float v1 = acc[mf][nf][half * 2 + 1] * rs + bc1;
                __half2 hv = __floats2half2_rn(v0, v1);
                *(__half2*)&HSs[rl][col] = hv;
                if (rg < NN_)
                    *(__half2*)(hs_out + (size_t)rg * HH_ + col) = hv;
            }
        }
    }
    // load W1 (64 rows x 128 halves) into Bs while epilogue settles
    {
        int n = tid >> 2;
        int qk = (tid & 3) * 32;
        unsigned sb = smem_u32(&Bs[n][qk]);
        const __half* gp = W1 + (size_t)n * HH_ + qk;
#pragma unroll
        for (int j = 0; j < 4; j++) cp16(sb + j * 16, gp + j * 8);
        cp_commit();
        cp_wait<0>();
    }
    __syncthreads();   // HSs + W1 visible to all

    // ---- stage 2: t = tanh(hs @ W1 + b1); s = t . w2 ----
    float acc2[2][4][4];
#pragma unroll
    for (int mf = 0; mf < 2; mf++)
#pragma unroll
        for (int nf = 0; nf < 4; nf++)
#pragma unroll
            for (int qq = 0; qq < 4; qq++) acc2[mf][nf][qq] = 0.f;

    mma_k128<4>(HSs, mbase, Bs, wn * 32, acc2, lane);

    float part[2][2] = {{0.f, 0.f}, {0.f, 0.f}};
#pragma unroll
    for (int mf = 0; mf < 2; mf++)
#pragma unroll
        for (int nf = 0; nf < 4; nf++) {
            int col = wn * 32 + nf * 8 + tig * 2;
            float bc0 = b1[col], bc1 = b1[col + 1];
            float w20 = w2[col], w21 = w2[col + 1];
#pragma unroll
            for (int half = 0; half < 2; half++) {
                float v0 = tanhf(acc2[mf][nf][half * 2 + 0] + bc0);
                float v1 = tanhf(acc2[mf][nf][half * 2 + 1] + bc1);
                part[mf][half] += v0 * w20 + v1 * w21;
            }
        }
#pragma unroll
    for (int o = 1; o <= 2; o <<= 1) {
#pragma unroll
        for (int mf = 0; mf < 2; mf++)
#pragma unroll
            for (int half = 0; half < 2; half++)
                part[mf][half] += __shfl_xor_sync(0xffffffffu, part[mf][half], o);
    }
    if (tig == 0) {
#pragma unroll
        for (int mf = 0; mf < 2; mf++)
#pragma unroll
            for (int half = 0; half < 2; half++)
                atomicAdd(&s_sm[mbase + mf * 16 + grp + half * 8], part[mf][half]);
    }
    __syncthreads();
    if (tid < 128) {
        int rg = block_m + tid;
        if (rg < NN_) s_out[rg] = s_sm[tid];
    }
}

// ---------------- batched attention combine (fp16 hs/out) -------------------
template <int PHASE>
__global__ void combine_all_kernel(const __half* __restrict__ hs_all,
                                   const float* __restrict__ s_all,
                                   __half* __restrict__ h1b, __half* __restrict__ hAb,
                                   __half* __restrict__ h2b) {
    const int u = blockIdx.y;
    int q0, c;
    __half* outb;
    if (PHASE == 0) {
        c = u >> 1;
        int li = u & 1;
        q0 = c * 4 + li * 2;
        outb = (li == 0 ? h1b : hAb);
    } else {
        c = u;
        q0 = c * 2;
        outb = h2b;
    }
    const __half* hs0 = hs_all + (size_t)q0 * NH_;
    const __half* hs1 = hs_all + (size_t)(q0 + 1) * NH_;
    const float* s0 = s_all + (size_t)q0 * NN_;
    const float* s1 = s_all + (size_t)(q0 + 1) * NN_;
    __half* out = outb + (size_t)c * NH_;

    int warp = (blockIdx.x * blockDim.x + threadIdx.x) >> 5;
    int lane = threadIdx.x & 31;
    if (warp >= NN_) return;
    float sv0 = s0[warp], sv1 = s1[warp];
    float m = fmaxf(sv0, sv1);
    float e0 = expf(sv0 - m), e1 = expf(sv1 - m);
    float a0 = e0 / (e0 + e1), a1 = 1.f - a0;
    uint2 u0 = ((const uint2*)(hs0 + (size_t)warp * HH_))[lane];
    uint2 u1 = ((const uint2*)(hs1 + (size_t)warp * HH_))[lane];
    float2 f0a = __half22float2(*(__half2*)&u0.x);
    float2 f0b = __half22float2(*(__half2*)&u0.y);
    float2 f1a = __half22float2(*(__half2*)&u1.x);
    float2 f1b = __half22float2(*(__half2*)&u1.y);
    uint2 st;
    *(__half2*)&st.x = __floats2half2_rn(a0 * f0a.x + a1 * f1a.x, a0 * f0a.y + a1 * f1a.y);
    *(__half2*)&st.y = __floats2half2_rn(a0 * f0b.x + a1 * f1b.x, a0 * f0b.y + a1 * f1b.y);
    ((uint2*)(out + (size_t)warp * HH_))[lane] = st;
}

// ---------------- final GEMM: y = [h0|h1|h2](fp16) @ Wc16^T -> fp32 ---------
__global__ __launch_bounds__(256)
void final_gemm_kernel(const __half* __restrict__ h0b, const __half* __restrict__ h1b,
                       const __half* __restrict__ h2b, const __half* __restrict__ wc16,
                       float* __restrict__ Cout) {
    extern __shared__ char smraw[];
    __half (*As)[TP] = (__half(*)[TP])(smraw);
    __half (*Bs)[TP] = (__half(*)[TP])(smraw + 128 * TP * 2);

    const int c = blockIdx.y;
    const int s = c >> 1;
    const __half* B = wc16 + (size_t)s * HH_ * (3 * HH_);
    float* C = Cout + (size_t)c * NH_;

    const int tid  = threadIdx.x;
    const int lane = tid & 31;
    const int warp = tid >> 5;
    const int grp  = lane >> 2;
    const int tig  = lane & 3;
    const int mbase = (warp >> 1) * 32;
    const int nbase = (warp & 1) * 64;
    const int block_m = blockIdx.x * 128;

    const __half* segs[3] = { h0b + (size_t)c * NH_, h1b + (size_t)c * NH_,
                              h2b + (size_t)c * NH_ };

    float acc[2][8][4];
#pragma unroll
    for (int mf = 0; mf < 2; mf++)
#pragma unroll
        for (int nf = 0; nf < 8; nf++)
#pragma unroll
            for (int q = 0; q < 4; q++) acc[mf][nf][q] = 0.f;

#pragma unroll
    for (int k = 0; k < 3; k++) {
        copy128_A(As, segs[k], HH_, block_m, 0, tid, NN_);
        copy128_B(Bs, B, 3 * HH_, k * 128, tid);
        cp_commit();
        cp_wait<0>();
        __syncthreads();
        mma_k128<8>(As, mbase, Bs, nbase, acc, lane);
        __syncthreads();
    }
#pragma unroll
    for (int mf = 0; mf < 2; mf++) {
        int r0 = block_m + mbase + mf * 16 + grp;
#pragma unroll
        for (int nf = 0; nf < 8; nf++) {
            int col = nbase + nf * 8 + tig * 2;
#pragma unroll
            for (int half = 0; half < 2; half++) {
                int r = r0 + half * 8;
                if (r >= NN_) continue;
                float2 st;
                st.x = acc[mf][nf][half * 2 + 0];
                st.y = acc[mf][nf][half * 2 + 1];
                *(float2*)(C + (size_t)r * HH_ + col) = st;
            }
        }
    }
}

// ---------------- host orchestration ----------------------------------------
extern "C" void kernel_launch(void* const* d_in, const int* in_sizes, int n_in,
                              void* d_out, int out_size) {
    const float* x_attr  = (const float*)d_in[0];
    const float* x_stru  = (const float*)d_in[1];
    const int*   e_attr  = (const int*)  d_in[2];
    const int*   e_stru  = (const int*)  d_in[3];
    const float* Wf      = (const float*)d_in[4];
    const float* convW   = (const float*)d_in[5];
    const float* convB   = (const float*)d_in[6];
    const float* attnW1  = (const float*)d_in[7];
    const float* attnB1  = (const float*)d_in[8];
    const float* attnW2  = (const float*)d_in[9];
    const float* Wc      = (const float*)d_in[10];
    float* out = (float*)d_out;

    __half *h0, *h1, *hA, *h2, *agg, *hs, *x16, *wf16, *cw16, *w116, *wc16;
    float *sb, *din, *dout;
    int *cnt_in, *cnt_out, *cursor, *off, *csr;
    cudaGetSymbolAddress((void**)&h0,  g_h0);
    cudaGetSymbolAddress((void**)&h1,  g_h1);
    cudaGetSymbolAddress((void**)&hA,  g_hA);
    cudaGetSymbolAddress((void**)&h2,  g_h2);
    cudaGetSymbolAddress((void**)&agg, g_agg);
    cudaGetSymbolAddress((void**)&hs,  g_hs);
    cudaGetSymbolAddress((void**)&sb,  g_s);
    cudaGetSymbolAddress((void**)&x16, g_x16);
    cudaGetSymbolAddress((void**)&wf16, g_wf16);
    cudaGetSymbolAddress((void**)&cw16, g_cw16);
    cudaGetSymbolAddress((void**)&w116, g_w116);
    cudaGetSymbolAddress((void**)&wc16, g_wc16);
    cudaGetSymbolAddress((void**)&din,  g_din);
    cudaGetSymbolAddress((void**)&dout, g_dout);
    cudaGetSymbolAddress((void**)&cnt_in,  g_cnt_in);
    cudaGetSymbolAddress((void**)&cnt_out, g_cnt_out);
    cudaGetSymbolAddress((void**)&cursor,  g_cursor);
    cudaGetSymbolAddress((void**)&off, g_off);
    cudaGetSymbolAddress((void**)&csr, g_csr);

    const int TB = 256;
    const int gridM = (NN_ + 127) / 128;
    const int gridWarp = (NN_ + 7) / 8;
    const int GEMM_SMEM = 2 * 128 * TP * 2;                 // 69632 B
    const int HET_SMEM  = 3 * 128 * TP * 2 + 512;           // 104960 B
    cudaFuncSetAttribute(h0_gemm_kernel, cudaFuncAttributeMaxDynamicSharedMemorySize, GEMM_SMEM);
    cudaFuncSetAttribute(final_gemm_kernel, cudaFuncAttributeMaxDynamicSharedMemorySize, GEMM_SMEM);
    cudaFuncSetAttribute(het_all_kernel<0>, cudaFuncAttributeMaxDynamicSharedMemorySize, HET_SMEM);
    cudaFuncSetAttribute(het_all_kernel<1>, cudaFuncAttributeMaxDynamicSharedMemorySize, HET_SMEM);

    // 0) prep: weights fp16 [n][k], x fp16; zero counters
    prep_weights_kernel<<<256, TB>>>(Wf, convW, attnW1, Wc, wf16, cw16, w116, wc16);
    convert_x_kernel<<<512, TB>>>(x_attr, x_stru, x16);
    zero2_kernel<<<512, TB>>>(cnt_in, cnt_out, 8 * NN_);

    // 1) h0 for all 4 runs
    h0_gemm_kernel<<<dim3(gridM, 4), TB, GEMM_SMEM>>>(x16, wf16, h0);

    // 2) CSR build, all 8 pairs batched
    hist_all_kernel<<<dim3(256, 8), TB>>>(e_attr, e_stru, cnt_out, cnt_in);
    scan_deg_kernel<<<8, 1024>>>(cnt_in, cnt_out, off, cursor, din, dout);
    scatter_all_kernel<<<dim3(256, 8), TB>>>(e_attr, e_stru, cursor, csr);

    // 3) phase A: gather over h0 (8 pairs), het (16 combos), combine (8)
    gather_all_kernel<<<dim3(gridWarp, 8), TB>>>(h0, off, csr, dout, agg);
    het_all_kernel<0><<<dim3(gridM, 16), TB, HET_SMEM>>>(
        agg, cw16, convB, w116, attnB1, attnW2, din, hs, sb);
    combine_all_kernel<0><<<dim3(gridWarp, 8), TB>>>(hs, sb, h1, hA, h2);

    // 4) phase B: gather over hA (8), het (8), combine (4)
    gather_all_kernel<<<dim3(gridWarp, 8), TB>>>(hA, off, csr, dout, agg);
    het_all_kernel<1><<<dim3(gridM, 8), TB, HET_SMEM>>>(
        agg, cw16, convB, w116, attnB1, attnW2, din, hs, sb);
    combine_all_kernel<1><<<dim3(gridWarp, 4), TB>>>(hs, sb, h1, hA, h2);

    // 5) final: y = [h0|h1|h2] @ Wc^T for all 4 runs
    final_gemm_kernel<<<dim3(gridM, 4), TB, GEMM_SMEM>>>(h0, h1, h2, wc16, out);
}

// round 15
// speedup vs baseline: 1.0571x; 1.0571x over previous
#include <cuda_runtime.h>
#include <cuda_fp16.h>
#include <math.h>

// Problem constants
#define NN_ 50000
#define EE_ 600000
#define HH_ 128
#define FF_ 256
#define QQ_ 64
#define NH_ (NN_ * HH_)

// ---------------- scratch (device globals; no dynamic allocation) ----------
__device__ __half g_h0 [4 * NH_];
__device__ __half g_h1 [4 * NH_];
__device__ __half g_hA [4 * NH_];
__device__ __half g_h2 [4 * NH_];
__device__ __half g_agg[8 * NH_];
__device__ __half g_hs [16 * NH_];
__device__ float  g_s  [16 * NN_];
__device__ __half g_x16[2 * NN_ * FF_];          // fp16 copies of x_attr/x_stru

// fp16 weight copies, [n][k] layout (transposed where needed by prep kernel)
__device__ __half g_wf16 [2 * HH_ * FF_];        // [s][n=128][k=256]
__device__ __half g_cw16 [8 * HH_ * HH_];        // [m][n=128][k=128]
__device__ __half g_w116 [4 * QQ_ * HH_];        // [m][n=64][k=128]
__device__ __half g_wc16 [2 * HH_ * 3 * HH_];    // [s][n=128][k=384]

__device__ int   g_cnt_in [8 * NN_];
__device__ int   g_cnt_out[8 * NN_];
__device__ int   g_cursor [8 * NN_];
__device__ int   g_off    [8 * (NN_ + 1)];
__device__ int   g_csr    [8 * EE_];
__device__ float g_din    [8 * NN_];
__device__ float g_dout   [8 * NN_];

// ---------------- helpers ---------------------------------------------------
__device__ __forceinline__ const int* edge_ptr_dev(const int* e_attr, const int* e_stru,
                                                   int p, int which) {
    int c = p >> 1, r = p & 1;
    int sign = c >> 1;
    const int* E = (c & 1) ? e_stru : e_attr;
    return E + ((size_t)((sign * 2 + r) * 2 + which)) * EE_;
}

// ---------------- prep kernels ----------------------------------------------
__global__ void prep_weights_kernel(const float* __restrict__ Wf, const float* __restrict__ convW,
                                    const float* __restrict__ attnW1, const float* __restrict__ Wc,
                                    __half* __restrict__ wf16, __half* __restrict__ cw16,
                                    __half* __restrict__ w116, __half* __restrict__ wc16) {
    const int NWF = 2 * HH_ * FF_;
    const int NCW = 8 * HH_ * HH_;
    const int NW1 = 4 * QQ_ * HH_;
    const int NWC = 2 * HH_ * 3 * HH_;
    for (int i = blockIdx.x * blockDim.x + threadIdx.x;
         i < NWF + NCW + NW1 + NWC; i += gridDim.x * blockDim.x) {
        if (i < NWF) {
            wf16[i] = __float2half_rn(Wf[i]);
        } else if (i < NWF + NCW) {
            int j = i - NWF;
            int m = j / (HH_ * HH_), t = j % (HH_ * HH_);
            int n = t / HH_, k = t % HH_;
            cw16[j] = __float2half_rn(convW[m * HH_ * HH_ + k * HH_ + n]);
        } else if (i < NWF + NCW + NW1) {
            int j = i - NWF - NCW;
            int m = j / (QQ_ * HH_), t = j % (QQ_ * HH_);
            int n = t / HH_, k = t % HH_;
            w116[j] = __float2half_rn(attnW1[m * HH_ * QQ_ + k * QQ_ + n]);
        } else {
            int j = i - NWF - NCW - NW1;
            wc16[j] = __float2half_rn(Wc[j]);
        }
    }
}

__global__ void convert_x_kernel(const float* __restrict__ xa, const float* __restrict__ xs,
                                 __half* __restrict__ x16) {
    const int Q4 = NN_ * FF_ / 4;
    for (int i = blockIdx.x * blockDim.x + threadIdx.x; i < Q4; i += gridDim.x * blockDim.x) {
        float4 va = ((const float4*)xa)[i];
        float4 vs = ((const float4*)xs)[i];
        __half2 ha0 = __floats2half2_rn(va.x, va.y), ha1 = __floats2half2_rn(va.z, va.w);
        __half2 hs0 = __floats2half2_rn(vs.x, vs.y), hs1 = __floats2half2_rn(vs.z, vs.w);
        ((uint2*)x16)[i] = make_uint2(*(unsigned*)&ha0, *(unsigned*)&ha1);
        ((uint2*)(x16 + (size_t)NN_ * FF_))[i] = make_uint2(*(unsigned*)&hs0, *(unsigned*)&hs1);
    }
}

// ---------------- CSR-build kernels (batched over 8 pairs) ------------------
__global__ void zero_int_kernel(int* p, int n) {
    for (int i = blockIdx.x * blockDim.x + threadIdx.x; i < n; i += gridDim.x * blockDim.x)
        p[i] = 0;
}

__global__ void hist_all_kernel(const int* __restrict__ e_attr, const int* __restrict__ e_stru,
                                int* __restrict__ cnt_out, int* __restrict__ cnt_in) {
    int p = blockIdx.y;
    const int* src = edge_ptr_dev(e_attr, e_stru, p, 0);
    const int* dst = edge_ptr_dev(e_attr, e_stru, p, 1);
    int* co = cnt_out + p * NN_;
    int* ci = cnt_in  + p * NN_;
    for (int i = blockIdx.x * blockDim.x + threadIdx.x; i < EE_; i += gridDim.x * blockDim.x) {
        atomicAdd(&co[src[i]], 1);
        atomicAdd(&ci[dst[i]], 1);
    }
}

__global__ void deg_all_kernel(const int* __restrict__ cin, const int* __restrict__ cout,
                               float* __restrict__ din, float* __restrict__ dout) {
    for (int i = blockIdx.x * blockDim.x + threadIdx.x; i < 8 * NN_; i += gridDim.x * blockDim.x) {
        int a = cin[i];  if (a < 1) a = 1;
        int b = cout[i]; if (b < 1) b = 1;
        din [i] = rsqrtf((float)a);
        dout[i] = rsqrtf((float)b);
    }
}

__global__ void scan_all_kernel(const int* __restrict__ cnt_all, int* __restrict__ off_all,
                                int* __restrict__ cur_all) {
    __shared__ int sh[1024];
    const int p = blockIdx.x;
    const int* cnt = cnt_all + p * NN_;
    int* off = off_all + p * (NN_ + 1);
    int* cur = cur_all + p * NN_;
    const int t  = threadIdx.x;
    const int CH = (NN_ + 1023) / 1024;
    const int base = t * CH;
    int s = 0;
    for (int i = 0; i < CH; i++) { int idx = base + i; if (idx < NN_) s += cnt[idx]; }
    sh[t] = s;
    __syncthreads();
    for (int d = 1; d < 1024; d <<= 1) {
        int v = (t >= d) ? sh[t - d] : 0;
        __syncthreads();
        sh[t] += v;
        __syncthreads();
    }
    int run = (t == 0) ? 0 : sh[t - 1];
    for (int i = 0; i < CH; i++) {
        int idx = base + i;
        if (idx < NN_) { off[idx] = run; cur[idx] = run; run += cnt[idx]; }
    }
    if (t == 0) off[NN_] = sh[1023];
}

__global__ void scatter_all_kernel(const int* __restrict__ e_attr, const int* __restrict__ e_stru,
                                   int* __restrict__ cursor, int* __restrict__ csr) {
    int p = blockIdx.y;
    const int* src = edge_ptr_dev(e_attr, e_stru, p, 0);
    const int* dst = edge_ptr_dev(e_attr, e_stru, p, 1);
    int* cu = cursor + p * NN_;
    int* cs = csr + (size_t)p * EE_;
    for (int i = blockIdx.x * blockDim.x + threadIdx.x; i < EE_; i += gridDim.x * blockDim.x) {
        int pos = atomicAdd(&cu[dst[i]], 1);
        cs[pos] = src[i];
    }
}

// ---------------- batched CSR gather (warp per node, fp16 rows) — R10 -------
__global__ void gather_all_kernel(const __half* __restrict__ hin_base,
                                  const int* __restrict__ off_all,
                                  const int* __restrict__ csr_all,
                                  const float* __restrict__ dout_all,
                                  __half* __restrict__ agg) {
    int p = blockIdx.y;
    int c = p >> 1;
    const __half* h = hin_base + (size_t)c * NH_;
    const int* off = off_all + p * (NN_ + 1);
    const int* csr = csr_all + (size_t)p * EE_;
    const float* dout = dout_all + p * NN_;
    __half* out = agg + (size_t)p * NH_;

    int warp = (blockIdx.x * blockDim.x + threadIdx.x) >> 5;
    int lane = threadIdx.x & 31;
    if (warp >= NN_) return;
    int b = off[warp], e = off[warp + 1];
    const uint2* h4 = (const uint2*)h;
    float ax = 0.f, ay = 0.f, az = 0.f, aw = 0.f;
    int i = b;
    for (; i + 1 < e; i += 2) {
        int s0 = csr[i], s1 = csr[i + 1];
        float w0 = dout[s0], w1 = dout[s1];
        uint2 u0 = h4[(size_t)s0 * 32 + lane];
        uint2 u1 = h4[(size_t)s1 * 32 + lane];
        float2 a0 = __half22float2(*(__half2*)&u0.x);
        float2 b0 = __half22float2(*(__half2*)&u0.y);
        float2 a1 = __half22float2(*(__half2*)&u1.x);
        float2 b1 = __half22float2(*(__half2*)&u1.y);
        ax += w0 * a0.x + w1 * a1.x;
        ay += w0 * a0.y + w1 * a1.y;
        az += w0 * b0.x + w1 * b1.x;
        aw += w0 * b0.y + w1 * b1.y;
    }
    if (i < e) {
        int s0 = csr[i];
        float w0 = dout[s0];
        uint2 u0 = h4[(size_t)s0 * 32 + lane];
        float2 a0 = __half22float2(*(__half2*)&u0.x);
        float2 b0 = __half22float2(*(__half2*)&u0.y);
        ax += w0 * a0.x; ay += w0 * a0.y; az += w0 * b0.x; aw += w0 * b0.y;
    }
    uint2 st;
    *(__half2*)&st.x = __floats2half2_rn(ax, ay);
    *(__half2*)&st.y = __floats2half2_rn(az, aw);
    ((uint2*)out)[(size_t)warp * 32 + lane] = st;
}

// ---------------- fp16 MMA / async-copy / ldmatrix helpers ------------------
__device__ __forceinline__ void mma16(float* c, unsigned a0, unsigned a1, unsigned a2,
                                      unsigned a3, unsigned b0, unsigned b1) {
    asm volatile(
        "mma.sync.aligned.m16n8k16.row.col.f32.f16.f16.f32 "
        "{%0,%1,%2,%3},{%4,%5,%6,%7},{%8,%9},{%0,%1,%2,%3};"
        : "+f"(c[0]), "+f"(c[1]), "+f"(c[2]), "+f"(c[3])
        : "r"(a0), "r"(a1), "r"(a2), "r"(a3), "r"(b0), "r"(b1));
}

__device__ __forceinline__ unsigned smem_u32(const void* p) {
    return (unsigned)__cvta_generic_to_shared(p);
}
__device__ __forceinline__ void cp16(unsigned s, const void* g) {
    asm volatile("cp.async.ca.shared.global [%0], [%1], 16;" :: "r"(s), "l"(g));
}
__device__ __forceinline__ void cp_commit() { asm volatile("cp.async.commit_group;"); }
template <int N>
__device__ __forceinline__ void cp_wait() { asm volatile("cp.async.wait_group %0;" :: "n"(N)); }

__device__ __forceinline__ void ldsm4(unsigned& r0, unsigned& r1, unsigned& r2, unsigned& r3,
                                      unsigned a) {
    asm volatile("ldmatrix.sync.aligned.m8n8.x4.shared.b16 {%0,%1,%2,%3}, [%4];"
                 : "=r"(r0), "=r"(r1), "=r"(r2), "=r"(r3) : "r"(a));
}

#define AK 40      // 32-K chunk row pad: 80 B stride -> ldmatrix conflict-free
#define HSP 136    // hs row pad: 272 B stride -> conflict-free
#define TP 136     // whole-K=128 tile row pad

// ldmatrix.x4 address for the 16x16 tile at rows r0.., cols kk.. of T[.][S]
template <int S>
__device__ __forceinline__ unsigned frag_addr(const __half (*T)[S], int r0, int kk, int lane) {
    int lr = lane & 7;
    int sel = lane >> 3;
    int row = r0 + ((sel & 1) << 3) + lr;
    int col = kk + ((sel & 2) << 2);
    return smem_u32(&T[row][col]);
}

// one BK=32 chunk of MMA (R10 path)
template <int SA, int SB, int NF>
__device__ __forceinline__ void mma_tile(const __half (*Am)[SA], int akoff, int mbase,
                                         const __half (*Bm)[SB], int nbase,
                                         float (&acc)[2][NF][4], int lane) {
#pragma unroll
    for (int kk = 0; kk < 32; kk += 16) {
        unsigned a[2][4];
#pragma unroll
        for (int mf = 0; mf < 2; mf++)
            ldsm4(a[mf][0], a[mf][1], a[mf][2], a[mf][3],
                  frag_addr<SA>(Am, mbase + mf * 16, akoff + kk, lane));
        unsigned b0[NF], b1[NF];
#pragma unroll
        for (int pr = 0; pr < NF / 2; pr++)
            ldsm4(b0[2 * pr], b0[2 * pr + 1], b1[2 * pr], b1[2 * pr + 1],
                  frag_addr<SB>(Bm, nbase + pr * 16, kk, lane));
#pragma unroll
        for (int nf = 0; nf < NF; nf++) {
            mma16(acc[0][nf], a[0][0], a[0][1], a[0][2], a[0][3], b0[nf], b1[nf]);
            mma16(acc[1][nf], a[1][0], a[1][1], a[1][2], a[1][3], b0[nf], b1[nf]);
        }
    }
}

// full K=128 MMA pass over resident TP tiles (no syncs inside)
template <int NF>
__device__ __forceinline__ void mma_k128(const __half (*Am)[TP], int mbase,
                                         const __half (*Bm)[TP], int nbase,
                                         float (&acc)[2][NF][4], int lane) {
#pragma unroll
    for (int kk = 0; kk < 128; kk += 16) {
        unsigned a[2][4];
#pragma unroll
        for (int mf = 0; mf < 2; mf++)
            ldsm4(a[mf][0], a[mf][1], a[mf][2], a[mf][3],
                  frag_addr<TP>(Am, mbase + mf * 16, kk, lane));
        unsigned b0[NF], b1[NF];
#pragma unroll
        for (int pr = 0; pr < NF / 2; pr++)
            ldsm4(b0[2 * pr], b0[2 * pr + 1], b1[2 * pr], b1[2 * pr + 1],
                  frag_addr<TP>(Bm, nbase + pr * 16, kk, lane));
#pragma unroll
        for (int nf = 0; nf < NF; nf++) {
            mma16(acc[0][nf], a[0][0], a[0][1], a[0][2], a[0][3], b0[nf], b1[nf]);
            mma16(acc[1][nf], a[1][0], a[1][1], a[1][2], a[1][3], b0[nf], b1[nf]);
        }
    }
}

// 32-K chunk tile copies (R10 path)
__device__ __forceinline__ void copy_tile_A(__half (*dst)[AK], const __half* A, int ld,
                                            int block_m, int k0, int tid, int M) {
    int row = tid & 127;
    int hb = tid >> 7;
    int gm = block_m + row;
    unsigned sa = smem_u32(&dst[row][hb * 16]);
    if (gm < M) {
        const __half* gp = A + (size_t)gm * ld + k0 + hb * 16;
        cp16(sa, gp);
        cp16(sa + 16, gp + 8);
    } else {
        *(uint4*)&dst[row][hb * 16]     = make_uint4(0, 0, 0, 0);
        *(uint4*)&dst[row][hb * 16 + 8] = make_uint4(0, 0, 0, 0);
    }
}
__device__ __forceinline__ void copy_tile_B(__half (*dst)[AK], const __half* B, int ld,
                                            int k0, int tid) {
    int row = tid & 127;
    int hb = tid >> 7;
    unsigned sb = smem_u32(&dst[row][hb * 16]);
    const __half* gp = B + (size_t)row * ld + k0 + hb * 16;
    cp16(sb, gp);
    cp16(sb + 16, gp + 8);
}

// whole K=128 tile copies (winning R12 path for standalone GEMMs)
__device__ __forceinline__ void copy128_A(__half (*dst)[TP], const __half* A, int ld,
                                          int block_m, int k0, int tid, int M) {
    int row = tid & 127;
    int hb = tid >> 7;
    int gm = block_m + row;
    unsigned sa = smem_u32(&dst[row][hb * 64]);
    if (gm < M) {
        const __half* gp = A + (size_t)gm * ld + k0 + hb * 64;
#pragma unroll
        for (int j = 0; j < 8; j++) cp16(sa + j * 16, gp + j * 8);
    } else {
#pragma unroll
        for (int j = 0; j < 8; j++) *(uint4*)&dst[row][hb * 64 + j * 8] = make_uint4(0, 0, 0, 0);
    }
}
__device__ __forceinline__ void copy128_B(__half (*dst)[TP], const __half* B, int ld,
                                          int k0, int tid) {
    int row = tid & 127;
    int hb = tid >> 7;
    unsigned sb = smem_u32(&dst[row][hb * 64]);
    const __half* gp = B + (size_t)row * ld + k0 + hb * 64;
#pragma unroll
    for (int j = 0; j < 8; j++) cp16(sb + j * 16, gp + j * 8);
}

// ---------------- h0 GEMM: whole-K tiles (measured faster) ------------------
__global__ __launch_bounds__(256)
void h0_gemm_kernel(const __half* __restrict__ x16, const __half* __restrict__ wf16,
                    __half* __restrict__ h0b) {
    extern __shared__ char smraw[];
    __half (*As)[TP] = (__half(*)[TP])(smraw);
    __half (*Bs)[TP] = (__half(*)[TP])(smraw + 128 * TP * 2);

    const int c = blockIdx.y;
    const int s = c >> 1;
    const __half* A = x16 + (size_t)(c & 1) * NN_ * FF_;
    const __half* B = wf16 + (size_t)s * HH_ * FF_;
    __half* C = h0b + (size_t)c * NH_;

    const int tid  = threadIdx.x;
    const int lane = tid & 31;
    const int warp = tid >> 5;
    const int grp  = lane >> 2;
    const int tig  = lane & 3;
    const int mbase = (warp >> 1) * 32;
    const int nbase = (warp & 1) * 64;
    const int block_m = blockIdx.x * 128;

    float acc[2][8][4];
#pragma unroll
    for (int mf = 0; mf < 2; mf++)
#pragma unroll
        for (int nf = 0; nf < 8; nf++)
#pragma unroll
            for (int q = 0; q < 4; q++) acc[mf][nf][q] = 0.f;

#pragma unroll
    for (int k = 0; k < 2; k++) {
        copy128_A(As, A, FF_, block_m, k * 128, tid, NN_);
        copy128_B(Bs, B, FF_, k * 128, tid);
        cp_commit();
        cp_wait<0>();
        __syncthreads();
        mma_k128<8>(As, mbase, Bs, nbase, acc, lane);
        __syncthreads();
    }
#pragma unroll
    for (int mf = 0; mf < 2; mf++) {
        int r0 = block_m + mbase + mf * 16 + grp;
#pragma unroll
        for (int nf = 0; nf < 8; nf++) {
            int col = nbase + nf * 8 + tig * 2;
#pragma unroll
            for (int half = 0; half < 2; half++) {
                int r = r0 + half * 8;
                if (r >= NN_) continue;
                *(__half2*)(C + (size_t)r * HH_ + col) =
                    __floats2half2_rn(tanhf(acc[mf][nf][half * 2 + 0]),
                                      tanhf(acc[mf][nf][half * 2 + 1]));
            }
        }
    }
}

// ---------------- batched fused conv GEMM + attention score — R10 -----------
// PHASE 0: blockIdx.y = q in 0..15: c=q>>2, li=(q>>1)&1 (li=0 -> l=1, li=1 -> l=0), r=q&1
// PHASE 1: blockIdx.y = q in 0..7:  c=q>>1, r=q&1, l=1
template <int PHASE>
__global__ __launch_bounds__(256)
void het_all_kernel(const __half* __restrict__ agg,
                    const __half* __restrict__ cw16, const float* __restrict__ convB,
                    const __half* __restrict__ w116, const float* __restrict__ attnB1,
                    const float* __restrict__ attnW2,
                    const float* __restrict__ din_all,
                    __half* __restrict__ hs_all, float* __restrict__ s_all) {
    extern __shared__ char smraw[];
    __half (*As)[128][AK] = (__half(*)[128][AK])(smraw);
    __half (*Bs)[128][AK] = (__half(*)[128][AK])(smraw + 2 * 128 * AK * 2);
    __half (*HSs)[HSP]    = (__half(*)[HSP])   (smraw + 4 * 128 * AK * 2);
    float* s_sm = (float*)(smraw + 4 * 128 * AK * 2 + 128 * HSP * 2);

    const int q = blockIdx.y;
    int c, l, r;
    if (PHASE == 0) { c = q >> 2; l = ((q >> 1) & 1) ? 0 : 1; r = q & 1; }
    else            { c = q >> 1; l = 1; r = q & 1; }
    const int s = c >> 1;
    const int p = c * 2 + r;
    const int m1 = (s * 2 + l) * 2 + r;
    const int m2 = s * 2 + l;

    const __half* A   = agg + (size_t)p * NH_;
    const __half* W   = cw16 + (size_t)m1 * HH_ * HH_;
    const float* bias = convB + (size_t)m1 * HH_;
    const __half* W1  = w116 + (size_t)m2 * QQ_ * HH_;
    const float* b1   = attnB1 + (size_t)m2 * QQ_;
    const float* w2   = attnW2 + (size_t)m2 * QQ_;
    const float* din  = din_all + p * NN_;
    __half* hs_out = hs_all + (size_t)q * NH_;
    float* s_out  = s_all + (size_t)q * NN_;

    const int tid  = threadIdx.x;
    const int lane = tid & 31;
    const int warp = tid >> 5;
    const int grp  = lane >> 2;
    const int tig  = lane & 3;
    const int wn   = warp & 1;
    const int mbase = (warp >> 1) * 32;
    const int block_m = blockIdx.x * 128;

    if (tid < 128) s_sm[tid] = 0.f;

    // ---------------- stage 1: conv GEMM (K=128, N=128), double-buffered ----
    float acc[2][8][4];
#pragma unroll
    for (int mf = 0; mf < 2; mf++)
#pragma unroll
        for (int nf = 0; nf < 8; nf++)
#pragma unroll
            for (int qq = 0; qq < 4; qq++) acc[mf][nf][qq] = 0.f;

    copy_tile_A(As[0], A, HH_, block_m, 0, tid, NN_);
    copy_tile_B(Bs[0], W, HH_, 0, tid);
    cp_commit();
    for (int k = 0; k < 4; k++) {
        if (k + 1 < 4) {
            copy_tile_A(As[(k + 1) & 1], A, HH_, block_m, (k + 1) * 32, tid, NN_);
            copy_tile_B(Bs[(k + 1) & 1], W, HH_, (k + 1) * 32, tid);
            cp_commit();
            cp_wait<1>();
        } else {
            cp_wait<0>();
        }
        __syncthreads();
        mma_tile<AK, AK, 8>(As[k & 1], 0, mbase, Bs[k & 1], wn * 64, acc, lane);
        __syncthreads();
    }

    // stage-1 epilogue: hs = acc*din + b; fp16 global write + [row][col] smem
#pragma unroll
    for (int mf = 0; mf < 2; mf++) {
        int rl0 = mbase + mf * 16 + grp;
#pragma unroll
        for (int nf = 0; nf < 8; nf++) {
            int col = wn * 64 + nf * 8 + tig * 2;
            float bc0 = bias[col], bc1 = bias[col + 1];
#pragma unroll
            for (int half = 0; half < 2; half++) {
                int rl = rl0 + half * 8;
                int rg = block_m + rl;
                float rs = (rg < NN_) ? din[rg] : 0.f;
                float v0 = acc[mf][nf][half * 2 + 0] * rs + bc0;
                float v1 = acc[mf][nf][half * 2 + 1] * rs + bc1;
                __half2 hv = __floats2half2_rn(v0, v1);
                *(__half2*)&HSs[rl][col] = hv;
                if (rg < NN_)
                    *(__half2*)(hs_out + (size_t)rg * HH_ + col) = hv;
            }
        }
    }
    __syncthreads();

    // ---------------- stage 2: t = tanh(hs@W1 + b1); s = t.w2 ----------------
    float acc2[2][4][4];
#pragma unroll
    for (int mf = 0; mf < 2; mf++)
#pragma unroll
        for (int nf = 0; nf < 4; nf++)
#pragma unroll
            for (int qq = 0; qq < 4; qq++) acc2[mf][nf][qq] = 0.f;

    for (int k0 = 0; k0 < HH_; k0 += 32) {
        {
            int n = tid & 63;
            int kb = (tid >> 6) * 8;
            cp16(smem_u32(&Bs[0][n][kb]), W1 + (size_t)n * HH_ + k0 + kb);
            cp_commit();
            cp_wait<0>();
        }
        __syncthreads();
        mma_tile<HSP, AK, 4>(HSs, k0, mbase, Bs[0], wn * 32, acc2, lane);
        __syncthreads();
    }

    float part[2][2] = {{0.f, 0.f}, {0.f, 0.f}};
#pragma unroll
    for (int mf = 0; mf < 2; mf++)
#pragma unroll
        for (int nf = 0; nf < 4; nf++) {
            int col = wn * 32 + nf * 8 + tig * 2;
            float bc0 = b1[col], bc1 = b1[col + 1];
            float w20 = w2[col], w21 = w2[col + 1];
#pragma unroll
            for (int half = 0; half < 2; half++) {
                float v0 = tanhf(acc2[mf][nf][half * 2 + 0] + bc0);
                float v1 = tanhf(acc2[mf][nf][half * 2 + 1] + bc1);
                part[mf][half] += v0 * w20 + v1 * w21;
            }
        }
#pragma unroll
    for (int o = 1; o <= 2; o <<= 1) {
#pragma unroll
        for (int mf = 0; mf < 2; mf++)
#pragma unroll
            for (int half = 0; half < 2; half++)
                part[mf][half] += __shfl_xor_sync(0xffffffffu, part[mf][half], o);
    }
    if (tig == 0) {
#pragma unroll
        for (int mf = 0; mf < 2; mf++)
#pragma unroll
            for (int half = 0; half < 2; half++)
                atomicAdd(&s_sm[mbase + mf * 16 + grp + half * 8], part[mf][half]);
    }
    __syncthreads();
    if (tid < 128) {
        int rg = block_m + tid;
        if (rg < NN_) s_out[rg] = s_sm[tid];
    }
}

// ---------------- batched attention combine (fp16 hs/out) -------------------
template <int PHASE>
__global__ void combine_all_kernel(const __half* __restrict__ hs_all,
                                   const float* __restrict__ s_all,
                                   __half* __restrict__ h1b, __half* __restrict__ hAb,
                                   __half* __restrict__ h2b) {
    const int u = blockIdx.y;
    int q0, c;
    __half* outb;
    if (PHASE == 0) {
        c = u >> 1;
        int li = u & 1;
        q0 = c * 4 + li * 2;
        outb = (li == 0 ? h1b : hAb);
    } else {
        c = u;
        q0 = c * 2;
        outb = h2b;
    }
    const __half* hs0 = hs_all + (size_t)q0 * NH_;
    const __half* hs1 = hs_all + (size_t)(q0 + 1) * NH_;
    const float* s0 = s_all + (size_t)q0 * NN_;
    const float* s1 = s_all + (size_t)(q0 + 1) * NN_;
    __half* out = outb + (size_t)c * NH_;

    int warp = (blockIdx.x * blockDim.x + threadIdx.x) >> 5;
    int lane = threadIdx.x & 31;
    if (warp >= NN_) return;
    float sv0 = s0[warp], sv1 = s1[warp];
    float m = fmaxf(sv0, sv1);
    float e0 = expf(sv0 - m), e1 = expf(sv1 - m);
    float a0 = e0 / (e0 + e1), a1 = 1.f - a0;
    uint2 u0 = ((const uint2*)(hs0 + (size_t)warp * HH_))[lane];
    uint2 u1 = ((const uint2*)(hs1 + (size_t)warp * HH_))[lane];
    float2 f0a = __half22float2(*(__half2*)&u0.x);
    float2 f0b = __half22float2(*(__half2*)&u0.y);
    float2 f1a = __half22float2(*(__half2*)&u1.x);
    float2 f1b = __half22float2(*(__half2*)&u1.y);
    uint2 st;
    *(__half2*)&st.x = __floats2half2_rn(a0 * f0a.x + a1 * f1a.x, a0 * f0a.y + a1 * f1a.y);
    *(__half2*)&st.y = __floats2half2_rn(a0 * f0b.x + a1 * f1b.x, a0 * f0b.y + a1 * f1b.y);
    ((uint2*)(out + (size_t)warp * HH_))[lane] = st;
}

// ---------------- final GEMM: whole-K tiles ---------------------------------
__global__ __launch_bounds__(256)
void final_gemm_kernel(const __half* __restrict__ h0b, const __half* __restrict__ h1b,
                       const __half* __restrict__ h2b, const __half* __restrict__ wc16,
                       float* __restrict__ Cout) {
    extern __shared__ char smraw[];
    __half (*As)[TP] = (__half(*)[TP])(smraw);
    __half (*Bs)[TP] = (__half(*)[TP])(smraw + 128 * TP * 2);

    const int c = blockIdx.y;
    const int s = c >> 1;
    const __half* B = wc16 + (size_t)s * HH_ * (3 * HH_);
    float* C = Cout + (size_t)c * NH_;

    const int tid  = threadIdx.x;
    const int lane = tid & 31;
    const int warp = tid >> 5;
    const int grp  = lane >> 2;
    const int tig  = lane & 3;
    const int mbase = (warp >> 1) * 32;
    const int nbase = (warp & 1) * 64;
    const int block_m = blockIdx.x * 128;

    const __half* segs[3] = { h0b + (size_t)c * NH_, h1b + (size_t)c * NH_,
                              h2b + (size_t)c * NH_ };

    float acc[2][8][4];
#pragma unroll
    for (int mf = 0; mf < 2; mf++)
#pragma unroll
        for (int nf = 0; nf < 8; nf++)
#pragma unroll
            for (int q = 0; q < 4; q++) acc[mf][nf][q] = 0.f;

#pragma unroll
    for (int k = 0; k < 3; k++) {
        copy128_A(As, segs[k], HH_, block_m, 0, tid, NN_);
        copy128_B(Bs, B, 3 * HH_, k * 128, tid);
        cp_commit();
        cp_wait<0>();
        __syncthreads();
        mma_k128<8>(As, mbase, Bs, nbase, acc, lane);
        __syncthreads();
    }
#pragma unroll
    for (int mf = 0; mf < 2; mf++) {
        int r0 = block_m + mbase + mf * 16 + grp;
#pragma unroll
        for (int nf = 0; nf < 8; nf++) {
            int col = nbase + nf * 8 + tig * 2;
#pragma unroll
            for (int half = 0; half < 2; half++) {
                int r = r0 + half * 8;
                if (r >= NN_) continue;
                float2 st;
                st.x = acc[mf][nf][half * 2 + 0];
                st.y = acc[mf][nf][half * 2 + 1];
                *(float2*)(C + (size_t)r * HH_ + col) = st;
            }
        }
    }
}

// ---------------- host orchestration ----------------------------------------
extern "C" void kernel_launch(void* const* d_in, const int* in_sizes, int n_in,
                              void* d_out, int out_size) {
    const float* x_attr  = (const float*)d_in[0];
    const float* x_stru  = (const float*)d_in[1];
    const int*   e_attr  = (const int*)  d_in[2];
    const int*   e_stru  = (const int*)  d_in[3];
    const float* Wf      = (const float*)d_in[4];
    const float* convW   = (const float*)d_in[5];
    const float* convB   = (const float*)d_in[6];
    const float* attnW1  = (const float*)d_in[7];
    const float* attnB1  = (const float*)d_in[8];
    const float* attnW2  = (const float*)d_in[9];
    const float* Wc      = (const float*)d_in[10];
    float* out = (float*)d_out;

    __half *h0, *h1, *hA, *h2, *agg, *hs, *x16, *wf16, *cw16, *w116, *wc16;
    float *sb, *din, *dout;
    int *cnt_in, *cnt_out, *cursor, *off, *csr;
    cudaGetSymbolAddress((void**)&h0,  g_h0);
    cudaGetSymbolAddress((void**)&h1,  g_h1);
    cudaGetSymbolAddress((void**)&hA,  g_hA);
    cudaGetSymbolAddress((void**)&h2,  g_h2);
    cudaGetSymbolAddress((void**)&agg, g_agg);
    cudaGetSymbolAddress((void**)&hs,  g_hs);
    cudaGetSymbolAddress((void**)&sb,  g_s);
    cudaGetSymbolAddress((void**)&x16, g_x16);
    cudaGetSymbolAddress((void**)&wf16, g_wf16);
    cudaGetSymbolAddress((void**)&cw16, g_cw16);
    cudaGetSymbolAddress((void**)&w116, g_w116);
    cudaGetSymbolAddress((void**)&wc16, g_wc16);
    cudaGetSymbolAddress((void**)&din,  g_din);
    cudaGetSymbolAddress((void**)&dout, g_dout);
    cudaGetSymbolAddress((void**)&cnt_in,  g_cnt_in);
    cudaGetSymbolAddress((void**)&cnt_out, g_cnt_out);
    cudaGetSymbolAddress((void**)&cursor,  g_cursor);
    cudaGetSymbolAddress((void**)&off, g_off);
    cudaGetSymbolAddress((void**)&csr, g_csr);

    const int TB = 256;
    const int gridM = (NN_ + 127) / 128;
    const int gridWarp = (NN_ + 7) / 8;
    const int HET_SMEM  = 4 * 128 * AK * 2 + 128 * HSP * 2 + 512;  // ~74.5 KB -> 2 blocks/SM
    const int GEMM_SMEM = 2 * 128 * TP * 2;                        // 69632 B
    cudaFuncSetAttribute(het_all_kernel<0>, cudaFuncAttributeMaxDynamicSharedMemorySize, HET_SMEM);
    cudaFuncSetAttribute(het_all_kernel<1>, cudaFuncAttributeMaxDynamicSharedMemorySize, HET_SMEM);
    cudaFuncSetAttribute(h0_gemm_kernel, cudaFuncAttributeMaxDynamicSharedMemorySize, GEMM_SMEM);
    cudaFuncSetAttribute(final_gemm_kernel, cudaFuncAttributeMaxDynamicSharedMemorySize, GEMM_SMEM);

    // 0) prep: weights fp16 [n][k], x fp16
    prep_weights_kernel<<<256, TB>>>(Wf, convW, attnW1, Wc, wf16, cw16, w116, wc16);
    convert_x_kernel<<<512, TB>>>(x_attr, x_stru, x16);

    // 1) zero histogram counters
    zero_int_kernel<<<512, TB>>>(cnt_in, 8 * NN_);
    zero_int_kernel<<<512, TB>>>(cnt_out, 8 * NN_);

    // 2) h0 for all 4 runs (fp16 out)
    h0_gemm_kernel<<<dim3(gridM, 4), TB, GEMM_SMEM>>>(x16, wf16, h0);

    // 3) CSR build, all 8 pairs batched
    hist_all_kernel<<<dim3(256, 8), TB>>>(e_attr, e_stru, cnt_out, cnt_in);
    deg_all_kernel<<<(8 * NN_ + 255) / 256, TB>>>(cnt_in, cnt_out, din, dout);
    scan_all_kernel<<<8, 1024>>>(cnt_in, off, cursor);
    scatter_all_kernel<<<dim3(256, 8), TB>>>(e_attr, e_stru, cursor, csr);

    // 4) phase A: gather over h0 (8 pairs), het (16 combos), combine (8)
    gather_all_kernel<<<dim3(gridWarp, 8), TB>>>(h0, off, csr, dout, agg);
    het_all_kernel<0><<<dim3(gridM, 16), TB, HET_SMEM>>>(
        agg, cw16, convB, w116, attnB1, attnW2, din, hs, sb);
    combine_all_kernel<0><<<dim3(gridWarp, 8), TB>>>(hs, sb, h1, hA, h2);

    // 5) phase B: gather over hA (8), het (8), combine (4)
    gather_all_kernel<<<dim3(gridWarp, 8), TB>>>(hA, off, csr, dout, agg);
    het_all_kernel<1><<<dim3(gridM, 8), TB, HET_SMEM>>>(
        agg, cw16, convB, w116, attnB1, attnW2, din, hs, sb);
    combine_all_kernel<1><<<dim3(gridWarp, 4), TB>>>(hs, sb, h1, hA, h2);

    // 6) final: y = [h0|h1|h2] @ Wc^T for all 4 runs (fp32 out)
    final_gemm_kernel<<<dim3(gridM, 4), TB, GEMM_SMEM>>>(h0, h1, h2, wc16, out);
}